// round 7
// baseline (speedup 1.0000x reference)
#include <cuda_runtime.h>
#include <cuda_bf16.h>
#include <cstdint>

#define WARPS_PER_CTA 2
#define ROWS_PER_WARP 8
// per-warp scratch layout (floats):
// [0,1024)    ptsXY: pair P(0..3), point p(0..63): [x0,x1,y0,y1]   (later act[128] A/B halves)
// [1024,1536) ptsZ : pair P, point p: [z0,z1]
// [1536,1920) vA: ring-major i'=ch*3+ring (0..95) x rows0..3  (later h1A[64]x4, h3A[16]x4)
// [1920,2304) vB: same, rows4..7                              (later h1B, h3B)
#define BUF_FLOATS 2304

typedef unsigned long long u64;

__device__ __forceinline__ u64 fma2(u64 a, u64 b, u64 c) {
    u64 d;
    asm("fma.rn.f32x2 %0, %1, %2, %3;" : "=l"(d) : "l"(a), "l"(b), "l"(c));
    return d;
}
__device__ __forceinline__ u64 pack2(float x, float y) {
    u64 d;
    asm("mov.b64 %0, {%1, %2};" : "=l"(d) : "r"(__float_as_uint(x)), "r"(__float_as_uint(y)));
    return d;
}
__device__ __forceinline__ u64 splat2(float x) {
    u64 d;
    asm("mov.b64 %0, {%1, %1};" : "=l"(d) : "r"(__float_as_uint(x)));
    return d;
}
__device__ __forceinline__ void unpack2(u64 a, float& x, float& y) {
    unsigned lo, hi;
    asm("mov.b64 {%0, %1}, %2;" : "=r"(lo), "=r"(hi) : "l"(a));
    x = __uint_as_float(lo); y = __uint_as_float(hi);
}
// No max.f32x2 in PTX: two scalar FMNMX (alu pipe); movs fold into reg-pair alloc.
__device__ __forceinline__ u64 max2(u64 a, u64 b) {
    float a0, a1, b0, b1;
    unpack2(a, a0, a1); unpack2(b, b0, b1);
    return pack2(fmaxf(a0, b0), fmaxf(a1, b1));
}
__device__ __forceinline__ u64 relu2(u64 x) {
    float x0, x1;
    unpack2(x, x0, x1);
    return pack2(fmaxf(x0, 0.f), fmaxf(x1, 0.f));
}
__device__ __forceinline__ u64 leaky2(u64 x) {
    float x0, x1;
    unpack2(x, x0, x1);
    return pack2(fmaxf(x0, 0.2f * x0), fmaxf(x1, 0.2f * x1));
}

__global__ __launch_bounds__(WARPS_PER_CTA * 32)
void flatnet_r7_kernel(
    const float* __restrict__ pgi,
    const float* __restrict__ W_lift, const float* __restrict__ b_lift,
    const float* __restrict__ W_code, const float* __restrict__ b_code,
    const float* __restrict__ W_h1,   const float* __restrict__ b_h1,
    const float* __restrict__ W_h2,   const float* __restrict__ b_h2,
    const float* __restrict__ W_h3,   const float* __restrict__ b_h3,
    const float* __restrict__ W_h4,   const float* __restrict__ b_h4,
    float* __restrict__ out)
{
    __shared__ __align__(16) float sbuf[WARPS_PER_CTA][BUF_FLOATS];

    const int warp = threadIdx.x >> 5;
    const int lane = threadIdx.x & 31;
    const int wrow = (blockIdx.x * WARPS_PER_CTA + warp) * ROWS_PER_WARP; // base row = b*1024+g
    float* buf = sbuf[warp];

    const int ld3 = lane / 3, lm3 = lane - ld3 * 3;

    // ---- Stage 8 rows' 8x8 point blocks (evict-first: pgi is a one-touch stream) ----
    {
        const int b = wrow >> 10, g = wrow & 1023;
        const int gi = g >> 5, gj = g & 31;          // gj..gj+7 never wraps (wrow mult of 8)
        const float* base = pgi + ((size_t)b * 65536 + (size_t)(gi * 8) * 256 + (size_t)(gj * 8)) * 3;
        if (lane < 24) {
            #pragma unroll
            for (int q = 0; q < ROWS_PER_WARP; q++) {
                const int P = q >> 1, s = q & 1;
                const float* bq = base + q * 24;
                #pragma unroll
                for (int gr = 0; gr < 8; gr++) {
                    const float val = __ldcs(bq + (size_t)gr * 768 + lane);
                    const int p = gr * 8 + ld3;
                    int off;
                    if (lm3 == 2) off = 1024 + P * 128 + p * 2 + s;       // z
                    else          off = P * 256 + p * 4 + lm3 * 2 + s;    // x / y
                    buf[off] = val;
                }
            }
        }
    }
    __syncwarp();

    // ---- Lift (lane = channel), row-pairs packed in f32x2; ring-major v stores ----
    {
        const u64 ww0 = splat2(__ldg(W_lift + lane));
        const u64 ww1 = splat2(__ldg(W_lift + 32 + lane));
        const u64 ww2 = splat2(__ldg(W_lift + 64 + lane));
        const u64 bb  = splat2(__ldg(b_lift + lane));

        #pragma unroll
        for (int P = 0; P < 4; P++) {
            const float* XY = buf + P * 256;
            const float* Z  = buf + 1024 + P * 128;
            u64 mi = pack2(-3.0e38f, -3.0e38f);
            u64 mt = mi, mo = mi;
            #pragma unroll
            for (int p = 0; p < 64; p += 2) {
                const ulonglong2 xyA = *(const ulonglong2*)(XY + p * 4);
                const ulonglong2 xyB = *(const ulonglong2*)(XY + p * 4 + 4);
                const ulonglong2 zz  = *(const ulonglong2*)(Z + p * 2);
                const u64 hA = fma2(xyA.x, ww0, fma2(xyA.y, ww1, fma2(zz.x, ww2, bb)));
                const u64 hB = fma2(xyB.x, ww0, fma2(xyB.y, ww1, fma2(zz.y, ww2, bb)));
                {
                    const int r = p >> 3, c = p & 7;
                    const int d = min(min(r, c), min(7 - r, 7 - c));
                    if (d == 3)      mi = max2(mi, hA);
                    else if (d == 2) mt = max2(mt, hA);
                    else             mo = max2(mo, hA);
                }
                {
                    const int r = (p + 1) >> 3, c = (p + 1) & 7;
                    const int d = min(min(r, c), min(7 - r, 7 - c));
                    if (d == 3)      mi = max2(mi, hB);
                    else if (d == 2) mt = max2(mt, hB);
                    else             mo = max2(mo, hB);
                }
            }
            // v' index: i' = lane*3 + ring (ring 0=inner,1=inter,2=outer)
            float* vdst = buf + ((P < 2) ? 1536 : 1920);
            const int qb = (P & 1) * 2;
            *(u64*)(vdst + (lane * 3 + 0) * 4 + qb) = leaky2(mi);
            *(u64*)(vdst + (lane * 3 + 1) * 4 + qb) = leaky2(mt);
            *(u64*)(vdst + (lane * 3 + 2) * 4 + qb) = leaky2(mo);
        }
    }
    __syncwarp();

    // ---- v_code[128] = leaky(v @ W_code + b); lane owns 4 CONSECUTIVE channels
    //      4*lane..4*lane+3 (float4 weight loads). v ring-major: W_code row = ring*32+ch. ----
    {
        u64 aA[4][2], aB[4][2];
        {
            const float4 b4 = __ldg((const float4*)(b_code + 4 * lane));
            aA[0][0] = splat2(b4.x); aA[1][0] = splat2(b4.y);
            aA[2][0] = splat2(b4.z); aA[3][0] = splat2(b4.w);
            #pragma unroll
            for (int c = 0; c < 4; c++) { aA[c][1] = aA[c][0]; aB[c][0] = aA[c][0]; aB[c][1] = aA[c][0]; }
        }
        #pragma unroll 2
        for (int ch = 0; ch < 32; ch++) {
            #pragma unroll
            for (int ring = 0; ring < 3; ring++) {
                const int ii = ch * 3 + ring;
                const ulonglong2 vA = *(const ulonglong2*)(buf + 1536 + ii * 4);
                const ulonglong2 vB = *(const ulonglong2*)(buf + 1920 + ii * 4);
                const float4 w4 = __ldg((const float4*)(W_code + (ring * 32 + ch) * 128 + 4 * lane));
                const u64 w0 = splat2(w4.x), w1 = splat2(w4.y), w2 = splat2(w4.z), w3 = splat2(w4.w);
                aA[0][0] = fma2(vA.x, w0, aA[0][0]); aA[0][1] = fma2(vA.y, w0, aA[0][1]);
                aB[0][0] = fma2(vB.x, w0, aB[0][0]); aB[0][1] = fma2(vB.y, w0, aB[0][1]);
                aA[1][0] = fma2(vA.x, w1, aA[1][0]); aA[1][1] = fma2(vA.y, w1, aA[1][1]);
                aB[1][0] = fma2(vB.x, w1, aB[1][0]); aB[1][1] = fma2(vB.y, w1, aB[1][1]);
                aA[2][0] = fma2(vA.x, w2, aA[2][0]); aA[2][1] = fma2(vA.y, w2, aA[2][1]);
                aB[2][0] = fma2(vB.x, w2, aB[2][0]); aB[2][1] = fma2(vB.y, w2, aB[2][1]);
                aA[3][0] = fma2(vA.x, w3, aA[3][0]); aA[3][1] = fma2(vA.y, w3, aA[3][1]);
                aB[3][0] = fma2(vB.x, w3, aB[3][0]); aB[3][1] = fma2(vB.y, w3, aB[3][1]);
            }
        }
        __syncwarp();
        #pragma unroll
        for (int c = 0; c < 4; c++) {
            const int ch = 4 * lane + c;
            ulonglong2 rA = { leaky2(aA[c][0]), leaky2(aA[c][1]) };
            ulonglong2 rB = { leaky2(aB[c][0]), leaky2(aB[c][1]) };
            *(ulonglong2*)(buf + ch * 4)       = rA;   // act rows 0-3
            *(ulonglong2*)(buf + 512 + ch * 4) = rB;   // act rows 4-7
        }
    }
    __syncwarp();

    // ---- h1[64] = relu(v_code @ W_h1 + b); lane owns lane, lane+32 ----
    {
        u64 cA[2][2], cB[2][2];
        #pragma unroll
        for (int o = 0; o < 2; o++) {
            const u64 bsp = splat2(__ldg(b_h1 + 32 * o + lane));
            cA[o][0] = bsp; cA[o][1] = bsp;
            cB[o][0] = bsp; cB[o][1] = bsp;
        }
        #pragma unroll 4
        for (int i = 0; i < 128; i++) {
            const ulonglong2 vA = *(const ulonglong2*)(buf + i * 4);
            const ulonglong2 vB = *(const ulonglong2*)(buf + 512 + i * 4);
            const float* wr = W_h1 + i * 64 + lane;
            #pragma unroll
            for (int o = 0; o < 2; o++) {
                const u64 ww = splat2(__ldg(wr + 32 * o));
                cA[o][0] = fma2(vA.x, ww, cA[o][0]);
                cA[o][1] = fma2(vA.y, ww, cA[o][1]);
                cB[o][0] = fma2(vB.x, ww, cB[o][0]);
                cB[o][1] = fma2(vB.y, ww, cB[o][1]);
            }
        }
        __syncwarp();
        #pragma unroll
        for (int o = 0; o < 2; o++) {
            const int ch = 32 * o + lane;
            ulonglong2 rA = { relu2(cA[o][0]), relu2(cA[o][1]) };
            ulonglong2 rB = { relu2(cB[o][0]), relu2(cB[o][1]) };
            *(ulonglong2*)(buf + 1536 + ch * 4) = rA;  // h1A
            *(ulonglong2*)(buf + 1792 + ch * 4) = rB;  // h1B
        }
    }
    __syncwarp();

    // ---- h2[32] = relu(h1 @ W_h2 + b) ----
    {
        u64 dA[2], dB[2];
        {
            const u64 bsp = splat2(__ldg(b_h2 + lane));
            dA[0] = bsp; dA[1] = bsp;
            dB[0] = bsp; dB[1] = bsp;
        }
        #pragma unroll 8
        for (int i = 0; i < 64; i++) {
            const ulonglong2 vA = *(const ulonglong2*)(buf + 1536 + i * 4);
            const ulonglong2 vB = *(const ulonglong2*)(buf + 1792 + i * 4);
            const u64 ww = splat2(__ldg(W_h2 + i * 32 + lane));
            dA[0] = fma2(vA.x, ww, dA[0]);
            dA[1] = fma2(vA.y, ww, dA[1]);
            dB[0] = fma2(vB.x, ww, dB[0]);
            dB[1] = fma2(vB.y, ww, dB[1]);
        }
        __syncwarp();
        ulonglong2 rA = { relu2(dA[0]), relu2(dA[1]) };
        ulonglong2 rB = { relu2(dB[0]), relu2(dB[1]) };
        *(ulonglong2*)(buf + lane * 4)       = rA;     // h2A
        *(ulonglong2*)(buf + 128 + lane * 4) = rB;     // h2B
    }
    __syncwarp();

    // ---- h3[16] = relu(h2 @ W_h3 + b); half-warp handles rows0-3 / rows4-7 ----
    {
        const int j  = lane & 15;
        const int hh = lane >> 4;
        u64 e0, e1;
        {
            const u64 bsp = splat2(__ldg(b_h3 + j));
            e0 = bsp; e1 = bsp;
        }
        const float* h2p = buf + hh * 128;
        #pragma unroll 8
        for (int i = 0; i < 32; i++) {
            const ulonglong2 v = *(const ulonglong2*)(h2p + i * 4);
            const u64 ww = splat2(__ldg(W_h3 + i * 16 + j));
            e0 = fma2(v.x, ww, e0);
            e1 = fma2(v.y, ww, e1);
        }
        ulonglong2 r = { relu2(e0), relu2(e1) };
        *(ulonglong2*)(buf + (hh ? 1600 : 1536) + j * 4) = r;  // h3A / h3B
    }
    __syncwarp();

    // ---- out[3] per row; lanes 0..23: q=ld3, comp=lm3 -> 24 contiguous floats ----
    if (lane < 24) {
        const float* h3p = buf + ((ld3 < 4) ? (1536 + ld3) : (1600 + (ld3 - 4)));
        float o = __ldg(b_h4 + lm3);
        #pragma unroll
        for (int i = 0; i < 16; i++)
            o = fmaf(h3p[i * 4], __ldg(W_h4 + i * 3 + lm3), o);
        out[(size_t)wrow * 3 + lane] = o;
    }
}

extern "C" void kernel_launch(void* const* d_in, const int* in_sizes, int n_in,
                              void* d_out, int out_size)
{
    const float* pgi    = (const float*)d_in[0];
    const float* W_lift = (const float*)d_in[1];
    const float* b_lift = (const float*)d_in[2];
    const float* W_code = (const float*)d_in[3];
    const float* b_code = (const float*)d_in[4];
    const float* W_h1   = (const float*)d_in[5];
    const float* b_h1   = (const float*)d_in[6];
    const float* W_h2   = (const float*)d_in[7];
    const float* b_h2   = (const float*)d_in[8];
    const float* W_h3   = (const float*)d_in[9];
    const float* b_h3   = (const float*)d_in[10];
    const float* W_h4   = (const float*)d_in[11];
    const float* b_h4   = (const float*)d_in[12];
    float* out = (float*)d_out;

    // Cap the smem carveout at ~50% so L1D (~114KB) can hold the ~91KB weight set.
    // Without this, 10+ resident CTAs x 18KB squeeze L1D to ~44KB and every weight
    // LDG becomes a 234-cycle L2 hit. Idempotent; safe under graph capture.
    cudaFuncSetAttribute(flatnet_r7_kernel,
                         cudaFuncAttributePreferredSharedMemoryCarveout, 50);

    // 32768 rows, 8 rows/warp, 2 warps/CTA -> 2048 CTAs x 64 threads
    flatnet_r7_kernel<<<2048, WARPS_PER_CTA * 32>>>(
        pgi, W_lift, b_lift, W_code, b_code,
        W_h1, b_h1, W_h2, b_h2, W_h3, b_h3, W_h4, b_h4, out);
}

// round 8
// speedup vs baseline: 1.0870x; 1.0870x over previous
#include <cuda_runtime.h>
#include <cuda_bf16.h>
#include <cstdint>

#define WARPS_PER_CTA 14
#define THREADS (WARPS_PER_CTA * 32)
#define N_GROUPS 4096              // 32768 rows / 8
#define ACTIVE_WARPS 2048          // each does exactly 2 groups

// Dynamic smem layout (float indices):
//  [0,12288)      W_code  96x128
//  [12288,20480)  W_h1   128x64
//  [20480,22528)  W_h2    64x32
//  [22528,23040)  W_h3    32x16
//  [23040,23088)  W_h4    16x3
//  [23088,23216)  b_code
//  [23216,23280)  b_h1
//  [23280,23312)  b_h2
//  [23312,23328)  b_h3
//  [23328,23331)  b_h4
//  [23344, +14*2304) per-warp buffers (16B aligned)
#define OFF_WC 0
#define OFF_W1 12288
#define OFF_W2 20480
#define OFF_W3 22528
#define OFF_W4 23040
#define OFF_BC 23088
#define OFF_B1 23216
#define OFF_B2 23280
#define OFF_B3 23312
#define OFF_B4 23328
#define OFF_BUF 23344
#define BUF_FLOATS 2304
#define SMEM_BYTES ((OFF_BUF + WARPS_PER_CTA * BUF_FLOATS) * 4)   // 222400

typedef unsigned long long u64;

__device__ __forceinline__ u64 fma2(u64 a, u64 b, u64 c) {
    u64 d;
    asm("fma.rn.f32x2 %0, %1, %2, %3;" : "=l"(d) : "l"(a), "l"(b), "l"(c));
    return d;
}
__device__ __forceinline__ u64 pack2(float x, float y) {
    u64 d;
    asm("mov.b64 %0, {%1, %2};" : "=l"(d) : "r"(__float_as_uint(x)), "r"(__float_as_uint(y)));
    return d;
}
__device__ __forceinline__ u64 splat2(float x) {
    u64 d;
    asm("mov.b64 %0, {%1, %1};" : "=l"(d) : "r"(__float_as_uint(x)));
    return d;
}
__device__ __forceinline__ void unpack2(u64 a, float& x, float& y) {
    unsigned lo, hi;
    asm("mov.b64 {%0, %1}, %2;" : "=r"(lo), "=r"(hi) : "l"(a));
    x = __uint_as_float(lo); y = __uint_as_float(hi);
}
__device__ __forceinline__ u64 max2(u64 a, u64 b) {
    float a0, a1, b0, b1;
    unpack2(a, a0, a1); unpack2(b, b0, b1);
    return pack2(fmaxf(a0, b0), fmaxf(a1, b1));
}
__device__ __forceinline__ u64 relu2(u64 x) {
    float x0, x1;
    unpack2(x, x0, x1);
    return pack2(fmaxf(x0, 0.f), fmaxf(x1, 0.f));
}
__device__ __forceinline__ u64 leaky2(u64 x) {
    float x0, x1;
    unpack2(x, x0, x1);
    return pack2(fmaxf(x0, 0.2f * x0), fmaxf(x1, 0.2f * x1));
}

__global__ __launch_bounds__(THREADS)
void flatnet_r8s_kernel(
    const float* __restrict__ pgi,
    const float* __restrict__ W_lift, const float* __restrict__ b_lift,
    const float* __restrict__ W_code, const float* __restrict__ b_code,
    const float* __restrict__ W_h1,   const float* __restrict__ b_h1,
    const float* __restrict__ W_h2,   const float* __restrict__ b_h2,
    const float* __restrict__ W_h3,   const float* __restrict__ b_h3,
    const float* __restrict__ W_h4,   const float* __restrict__ b_h4,
    float* __restrict__ out)
{
    extern __shared__ __align__(16) float dsm[];

    const int tid  = threadIdx.x;
    const int warp = tid >> 5;
    const int lane = tid & 31;

    // ---- Cooperative load of ALL weights into shared memory (once per CTA) ----
    for (int i = tid; i < 12288; i += THREADS) dsm[OFF_WC + i] = W_code[i];
    for (int i = tid; i < 8192;  i += THREADS) dsm[OFF_W1 + i] = W_h1[i];
    for (int i = tid; i < 2048;  i += THREADS) dsm[OFF_W2 + i] = W_h2[i];
    for (int i = tid; i < 512;   i += THREADS) dsm[OFF_W3 + i] = W_h3[i];
    if (tid < 48)  dsm[OFF_W4 + tid] = W_h4[tid];
    if (tid < 128) dsm[OFF_BC + tid] = b_code[tid];
    if (tid < 64)  dsm[OFF_B1 + tid] = b_h1[tid];
    if (tid < 32)  dsm[OFF_B2 + tid] = b_h2[tid];
    if (tid < 16)  dsm[OFF_B3 + tid] = b_h3[tid];
    if (tid < 3)   dsm[OFF_B4 + tid] = b_h4[tid];
    __syncthreads();

    const float* sWc = dsm + OFF_WC;
    const float* sW1 = dsm + OFF_W1;
    const float* sW2 = dsm + OFF_W2;
    const float* sW3 = dsm + OFF_W3;
    const float* sW4 = dsm + OFF_W4;

    const int wg = blockIdx.x * WARPS_PER_CTA + warp;   // 0 .. 2071
    if (wg >= ACTIVE_WARPS) return;

    float* buf = dsm + OFF_BUF + warp * BUF_FLOATS;
    const int ld3 = lane / 3, lm3 = lane - ld3 * 3;

    // lift weights stay in registers (tiny, L1-resident)
    const u64 ww0 = splat2(__ldg(W_lift + lane));
    const u64 ww1 = splat2(__ldg(W_lift + 32 + lane));
    const u64 ww2 = splat2(__ldg(W_lift + 64 + lane));
    const u64 bbl = splat2(__ldg(b_lift + lane));

    #pragma unroll 1
    for (int it = 0; it < 2; it++) {
        const int wrow = (wg * 2 + it) * 8;             // base row = b*1024+g

        // ---- Stage 8 rows' 8x8 point blocks (evict-first stream) ----
        {
            const int b = wrow >> 10, g = wrow & 1023;
            const int gi = g >> 5, gj = g & 31;
            const float* base = pgi + ((size_t)b * 65536 + (size_t)(gi * 8) * 256 + (size_t)(gj * 8)) * 3;
            if (lane < 24) {
                #pragma unroll
                for (int q = 0; q < 8; q++) {
                    const int P = q >> 1, s = q & 1;
                    const float* bq = base + q * 24;
                    #pragma unroll
                    for (int gr = 0; gr < 8; gr++) {
                        const float val = __ldcs(bq + (size_t)gr * 768 + lane);
                        const int p = gr * 8 + ld3;
                        int off;
                        if (lm3 == 2) off = 1024 + P * 128 + p * 2 + s;       // z
                        else          off = P * 256 + p * 4 + lm3 * 2 + s;    // x / y
                        buf[off] = val;
                    }
                }
            }
        }
        __syncwarp();

        // ---- Lift (lane = channel), row-pairs packed; ring-major v stores ----
        #pragma unroll
        for (int P = 0; P < 4; P++) {
            const float* XY = buf + P * 256;
            const float* Z  = buf + 1024 + P * 128;
            u64 mi = pack2(-3.0e38f, -3.0e38f);
            u64 mt = mi, mo = mi;
            #pragma unroll
            for (int p = 0; p < 64; p += 2) {
                const ulonglong2 xyA = *(const ulonglong2*)(XY + p * 4);
                const ulonglong2 xyB = *(const ulonglong2*)(XY + p * 4 + 4);
                const ulonglong2 zz  = *(const ulonglong2*)(Z + p * 2);
                const u64 hA = fma2(xyA.x, ww0, fma2(xyA.y, ww1, fma2(zz.x, ww2, bbl)));
                const u64 hB = fma2(xyB.x, ww0, fma2(xyB.y, ww1, fma2(zz.y, ww2, bbl)));
                {
                    const int r = p >> 3, c = p & 7;
                    const int d = min(min(r, c), min(7 - r, 7 - c));
                    if (d == 3)      mi = max2(mi, hA);
                    else if (d == 2) mt = max2(mt, hA);
                    else             mo = max2(mo, hA);
                }
                {
                    const int r = (p + 1) >> 3, c = (p + 1) & 7;
                    const int d = min(min(r, c), min(7 - r, 7 - c));
                    if (d == 3)      mi = max2(mi, hB);
                    else if (d == 2) mt = max2(mt, hB);
                    else             mo = max2(mo, hB);
                }
            }
            // v' index: i' = lane*3 + ring (ring 0=inner,1=inter,2=outer)
            float* vdst = buf + ((P < 2) ? 1536 : 1920);
            const int qb = (P & 1) * 2;
            *(u64*)(vdst + (lane * 3 + 0) * 4 + qb) = leaky2(mi);
            *(u64*)(vdst + (lane * 3 + 1) * 4 + qb) = leaky2(mt);
            *(u64*)(vdst + (lane * 3 + 2) * 4 + qb) = leaky2(mo);
        }
        __syncwarp();

        // ---- v_code[128] = leaky(v @ W_code + b); lane owns j=lane+32o.
        //      v ring-major: i'=ch*3+ring <-> W_code row = ring*32+ch (smem). ----
        {
            u64 aA[4][2], aB[4][2];
            #pragma unroll
            for (int o = 0; o < 4; o++) {
                const u64 bsp = splat2(dsm[OFF_BC + 32 * o + lane]);
                aA[o][0] = bsp; aA[o][1] = bsp;
                aB[o][0] = bsp; aB[o][1] = bsp;
            }
            #pragma unroll 2
            for (int ch = 0; ch < 32; ch++) {
                #pragma unroll
                for (int ring = 0; ring < 3; ring++) {
                    const int ii = ch * 3 + ring;
                    const ulonglong2 vA = *(const ulonglong2*)(buf + 1536 + ii * 4);
                    const ulonglong2 vB = *(const ulonglong2*)(buf + 1920 + ii * 4);
                    const float* wr = sWc + (ring * 32 + ch) * 128 + lane;
                    #pragma unroll
                    for (int o = 0; o < 4; o++) {
                        const u64 ww = splat2(wr[32 * o]);
                        aA[o][0] = fma2(vA.x, ww, aA[o][0]);
                        aA[o][1] = fma2(vA.y, ww, aA[o][1]);
                        aB[o][0] = fma2(vB.x, ww, aB[o][0]);
                        aB[o][1] = fma2(vB.y, ww, aB[o][1]);
                    }
                }
            }
            __syncwarp();
            #pragma unroll
            for (int o = 0; o < 4; o++) {
                const int ch = 32 * o + lane;
                ulonglong2 rA = { leaky2(aA[o][0]), leaky2(aA[o][1]) };
                ulonglong2 rB = { leaky2(aB[o][0]), leaky2(aB[o][1]) };
                *(ulonglong2*)(buf + ch * 4)       = rA;   // act rows 0-3
                *(ulonglong2*)(buf + 512 + ch * 4) = rB;   // act rows 4-7
            }
        }
        __syncwarp();

        // ---- h1[64] = relu(v_code @ W_h1 + b) ----
        {
            u64 cA[2][2], cB[2][2];
            #pragma unroll
            for (int o = 0; o < 2; o++) {
                const u64 bsp = splat2(dsm[OFF_B1 + 32 * o + lane]);
                cA[o][0] = bsp; cA[o][1] = bsp;
                cB[o][0] = bsp; cB[o][1] = bsp;
            }
            #pragma unroll 4
            for (int i = 0; i < 128; i++) {
                const ulonglong2 vA = *(const ulonglong2*)(buf + i * 4);
                const ulonglong2 vB = *(const ulonglong2*)(buf + 512 + i * 4);
                const float* wr = sW1 + i * 64 + lane;
                #pragma unroll
                for (int o = 0; o < 2; o++) {
                    const u64 ww = splat2(wr[32 * o]);
                    cA[o][0] = fma2(vA.x, ww, cA[o][0]);
                    cA[o][1] = fma2(vA.y, ww, cA[o][1]);
                    cB[o][0] = fma2(vB.x, ww, cB[o][0]);
                    cB[o][1] = fma2(vB.y, ww, cB[o][1]);
                }
            }
            __syncwarp();
            #pragma unroll
            for (int o = 0; o < 2; o++) {
                const int ch = 32 * o + lane;
                ulonglong2 rA = { relu2(cA[o][0]), relu2(cA[o][1]) };
                ulonglong2 rB = { relu2(cB[o][0]), relu2(cB[o][1]) };
                *(ulonglong2*)(buf + 1536 + ch * 4) = rA;  // h1A
                *(ulonglong2*)(buf + 1792 + ch * 4) = rB;  // h1B
            }
        }
        __syncwarp();

        // ---- h2[32] = relu(h1 @ W_h2 + b) ----
        {
            u64 dA[2], dB[2];
            {
                const u64 bsp = splat2(dsm[OFF_B2 + lane]);
                dA[0] = bsp; dA[1] = bsp;
                dB[0] = bsp; dB[1] = bsp;
            }
            #pragma unroll 8
            for (int i = 0; i < 64; i++) {
                const ulonglong2 vA = *(const ulonglong2*)(buf + 1536 + i * 4);
                const ulonglong2 vB = *(const ulonglong2*)(buf + 1792 + i * 4);
                const u64 ww = splat2(sW2[i * 32 + lane]);
                dA[0] = fma2(vA.x, ww, dA[0]);
                dA[1] = fma2(vA.y, ww, dA[1]);
                dB[0] = fma2(vB.x, ww, dB[0]);
                dB[1] = fma2(vB.y, ww, dB[1]);
            }
            __syncwarp();
            ulonglong2 rA = { relu2(dA[0]), relu2(dA[1]) };
            ulonglong2 rB = { relu2(dB[0]), relu2(dB[1]) };
            *(ulonglong2*)(buf + lane * 4)       = rA;     // h2A
            *(ulonglong2*)(buf + 128 + lane * 4) = rB;     // h2B
        }
        __syncwarp();

        // ---- h3[16] = relu(h2 @ W_h3 + b); half-warp per 4-row group ----
        {
            const int j  = lane & 15;
            const int hh = lane >> 4;
            u64 e0, e1;
            {
                const u64 bsp = splat2(dsm[OFF_B3 + j]);
                e0 = bsp; e1 = bsp;
            }
            const float* h2p = buf + hh * 128;
            #pragma unroll 8
            for (int i = 0; i < 32; i++) {
                const ulonglong2 v = *(const ulonglong2*)(h2p + i * 4);
                const u64 ww = splat2(sW3[i * 16 + j]);
                e0 = fma2(v.x, ww, e0);
                e1 = fma2(v.y, ww, e1);
            }
            ulonglong2 r = { relu2(e0), relu2(e1) };
            *(ulonglong2*)(buf + (hh ? 1600 : 1536) + j * 4) = r;  // h3A / h3B
        }
        __syncwarp();

        // ---- out[3] per row; lanes 0..23 -> 24 contiguous floats ----
        if (lane < 24) {
            const float* h3p = buf + ((ld3 < 4) ? (1536 + ld3) : (1600 + (ld3 - 4)));
            float o = dsm[OFF_B4 + lm3];
            #pragma unroll
            for (int i = 0; i < 16; i++)
                o = fmaf(h3p[i * 4], sW4[i * 3 + lm3], o);
            out[(size_t)wrow * 3 + lane] = o;
        }
        __syncwarp();
    }
}

extern "C" void kernel_launch(void* const* d_in, const int* in_sizes, int n_in,
                              void* d_out, int out_size)
{
    const float* pgi    = (const float*)d_in[0];
    const float* W_lift = (const float*)d_in[1];
    const float* b_lift = (const float*)d_in[2];
    const float* W_code = (const float*)d_in[3];
    const float* b_code = (const float*)d_in[4];
    const float* W_h1   = (const float*)d_in[5];
    const float* b_h1   = (const float*)d_in[6];
    const float* W_h2   = (const float*)d_in[7];
    const float* b_h2   = (const float*)d_in[8];
    const float* W_h3   = (const float*)d_in[9];
    const float* b_h3   = (const float*)d_in[10];
    const float* W_h4   = (const float*)d_in[11];
    const float* b_h4   = (const float*)d_in[12];
    float* out = (float*)d_out;

    cudaFuncSetAttribute(flatnet_r8s_kernel,
                         cudaFuncAttributeMaxDynamicSharedMemorySize, SMEM_BYTES);

    // 148 CTAs (1/SM) x 14 warps; warps 0..2047 each process exactly 2
    // consecutive 8-row groups -> 4096 groups = 32768 rows. No tail.
    flatnet_r8s_kernel<<<148, THREADS, SMEM_BYTES>>>(
        pgi, W_lift, b_lift, W_code, b_code,
        W_h1, b_h1, W_h2, b_h2, W_h3, b_h3, W_h4, b_h4, out);
}